// round 8
// baseline (speedup 1.0000x reference)
#include <cuda_runtime.h>
#include <math.h>

#define N_TOT 65536      // B(64) * C(1024) columns
#define S_DIM 576
#define H_DIM 72

// ---------------- scratch (device globals; no allocation allowed) ----------
__device__ float g_H1[H_DIM * N_TOT];          // 18.9 MB
__device__ float g_Y [H_DIM * N_TOT];          // 18.9 MB
__device__ float g_H2[H_DIM * N_TOT];          // 18.9 MB
__device__ float g_xm[N_TOT];
__device__ float g_out2[S_DIM * N_TOT];        // 151 MB
__device__ float g_psum[S_DIM * 512];          // BN partials per (s, ntile)
__device__ float g_psq [S_DIM * 512];
__device__ float g_M[H_DIM * H_DIM];
__device__ float g_yb[H_DIM];
__device__ float g_w2m[H_DIM];
__device__ float g_b2m;
__device__ float g_mu[S_DIM];
__device__ float g_rstd[S_DIM];

// ---------------- K0a: M = W3@W2 (72 blocks) -------------------------------
__global__ void __launch_bounds__(128) k0a_M(const float* __restrict__ W2,
                                             const float* __restrict__ W3)
{
    __shared__ float row[S_DIM];
    int o = blockIdx.x;
    for (int e = threadIdx.x; e < S_DIM; e += 128) row[e] = W3[o * S_DIM + e];
    __syncthreads();
    if (threadIdx.x < H_DIM) {
        int j = threadIdx.x;
        float a = 0.f;
        for (int s = 0; s < S_DIM; s++) a = fmaf(row[s], W2[s * H_DIM + j], a);
        g_M[o * H_DIM + j] = a;
    }
}

// ---------------- K0b: yb = W3@b2 ------------------------------------------
__global__ void __launch_bounds__(128) k0b_yb(const float* __restrict__ b2,
                                              const float* __restrict__ W3)
{
    __shared__ float bs[S_DIM];
    for (int e = threadIdx.x; e < S_DIM; e += 128) bs[e] = b2[e];
    __syncthreads();
    if (threadIdx.x < H_DIM) {
        int o = threadIdx.x;
        float a = 0.f;
        for (int s = 0; s < S_DIM; s++) a = fmaf(W3[o * S_DIM + s], bs[s], a);
        g_yb[o] = a;
    }
}

// ---------------- K0c: w2m = colmean(W2), b2m = mean(b2) -------------------
__global__ void __launch_bounds__(128) k0c_means(const float* __restrict__ W2,
                                                 const float* __restrict__ b2)
{
    if (threadIdx.x < H_DIM) {
        int j = threadIdx.x;
        float a = 0.f;
        for (int s = 0; s < S_DIM; s++) a += W2[s * H_DIM + j];
        g_w2m[j] = a * (1.f / (float)S_DIM);
    }
    if (threadIdx.x == H_DIM) {
        float a = 0.f;
        for (int s = 0; s < S_DIM; s++) a += b2[s];
        g_b2m = a * (1.f / (float)S_DIM);
    }
}

// ---------------- K1: fused gather + H1 = relu(W1 @ x_v + b1) --------------
// 128-col blocks, 9x4 register tile, 48-row s-tiles (12 phases)
// smem ~44.5 KB -> 5 blocks/SM for latency/barrier overlap
__global__ void __launch_bounds__(256) k1_gather_gemm1(
    const float* __restrict__ x,  const float* __restrict__ W1,
    const float* __restrict__ b1)
{
    __shared__ __align__(16) float wt[48 * 100];   // [sl][og*12 + k], 19.2 KB
    extern __shared__ __align__(16) float xt[];    // [48][132] = 25.3 KB dyn

    int n0 = blockIdx.x * 128;
    int B  = n0 >> 10;
    int c0 = n0 & 1023;
    int b = B & 15, chunk = B >> 4;
    int ty = (chunk >> 1) * 24, tx = (chunk & 1) * 24;
    int tid = threadIdx.x;
    int nl = tid & 31, og = tid >> 5;

    const float* xb = x + (b * 1024 + c0) * 2304 + ty * 48 + tx;

    float acc[9][4];
#pragma unroll
    for (int k = 0; k < 9; k++)
#pragma unroll
        for (int j = 0; j < 4; j++) acc[k][j] = 0.f;

    for (int t = 0; t < 12; t++) {
        // x tile: 48 s x 128 cols (sl fastest for coalesced 24-float runs)
        for (int e = tid; e < 48 * 128; e += 256) {
            int cl = e / 48, sl = e - cl * 48;
            int s = t * 48 + sl;
            int si = s / 24, sj = s - si * 24;
            xt[sl * 132 + cl] = xb[cl * 2304 + si * 48 + sj];
        }
        // weight tile transposed: wt[sl][(o/9)*12 + o%9]
        for (int e = tid; e < 72 * 48; e += 256) {
            int o = e / 48, sl = e - o * 48;
            int oq = o / 9, ok = o - oq * 9;
            wt[sl * 100 + oq * 12 + ok] = W1[o * S_DIM + t * 48 + sl];
        }
        __syncthreads();
#pragma unroll 4
        for (int sl = 0; sl < 48; sl++) {
            float4 av = *(const float4*)&xt[sl * 132 + nl * 4];
            const float* wp = &wt[sl * 100 + og * 12];
            float4 w0 = *(const float4*)wp;
            float4 w1 = *(const float4*)(wp + 4);
            float  w8 = wp[8];
            acc[0][0] = fmaf(w0.x, av.x, acc[0][0]); acc[0][1] = fmaf(w0.x, av.y, acc[0][1]);
            acc[0][2] = fmaf(w0.x, av.z, acc[0][2]); acc[0][3] = fmaf(w0.x, av.w, acc[0][3]);
            acc[1][0] = fmaf(w0.y, av.x, acc[1][0]); acc[1][1] = fmaf(w0.y, av.y, acc[1][1]);
            acc[1][2] = fmaf(w0.y, av.z, acc[1][2]); acc[1][3] = fmaf(w0.y, av.w, acc[1][3]);
            acc[2][0] = fmaf(w0.z, av.x, acc[2][0]); acc[2][1] = fmaf(w0.z, av.y, acc[2][1]);
            acc[2][2] = fmaf(w0.z, av.z, acc[2][2]); acc[2][3] = fmaf(w0.z, av.w, acc[2][3]);
            acc[3][0] = fmaf(w0.w, av.x, acc[3][0]); acc[3][1] = fmaf(w0.w, av.y, acc[3][1]);
            acc[3][2] = fmaf(w0.w, av.z, acc[3][2]); acc[3][3] = fmaf(w0.w, av.w, acc[3][3]);
            acc[4][0] = fmaf(w1.x, av.x, acc[4][0]); acc[4][1] = fmaf(w1.x, av.y, acc[4][1]);
            acc[4][2] = fmaf(w1.x, av.z, acc[4][2]); acc[4][3] = fmaf(w1.x, av.w, acc[4][3]);
            acc[5][0] = fmaf(w1.y, av.x, acc[5][0]); acc[5][1] = fmaf(w1.y, av.y, acc[5][1]);
            acc[5][2] = fmaf(w1.y, av.z, acc[5][2]); acc[5][3] = fmaf(w1.y, av.w, acc[5][3]);
            acc[6][0] = fmaf(w1.z, av.x, acc[6][0]); acc[6][1] = fmaf(w1.z, av.y, acc[6][1]);
            acc[6][2] = fmaf(w1.z, av.z, acc[6][2]); acc[6][3] = fmaf(w1.z, av.w, acc[6][3]);
            acc[7][0] = fmaf(w1.w, av.x, acc[7][0]); acc[7][1] = fmaf(w1.w, av.y, acc[7][1]);
            acc[7][2] = fmaf(w1.w, av.z, acc[7][2]); acc[7][3] = fmaf(w1.w, av.w, acc[7][3]);
            acc[8][0] = fmaf(w8,   av.x, acc[8][0]); acc[8][1] = fmaf(w8,   av.y, acc[8][1]);
            acc[8][2] = fmaf(w8,   av.z, acc[8][2]); acc[8][3] = fmaf(w8,   av.w, acc[8][3]);
        }
        __syncthreads();
    }
#pragma unroll
    for (int k = 0; k < 9; k++) {
        int o = og * 9 + k;
        float bb = b1[o];
        float4 v;
        v.x = fmaxf(acc[k][0] + bb, 0.f);
        v.y = fmaxf(acc[k][1] + bb, 0.f);
        v.z = fmaxf(acc[k][2] + bb, 0.f);
        v.w = fmaxf(acc[k][3] + bb, 0.f);
        *(float4*)&g_H1[o * N_TOT + n0 + nl * 4] = v;
    }
}

// ---------------- K2: Y = M@H1 + yb ;  x_m = w2m@H1 + b2m  [verbatim] ------
__global__ void __launch_bounds__(256) k2_Y_xm(void)
{
    __shared__ float Ms[H_DIM * H_DIM];
    __shared__ float ybs[H_DIM], w2ms[H_DIM];
    int tid = threadIdx.x;
    for (int e = tid; e < H_DIM * H_DIM; e += 256) Ms[e] = g_M[e];
    if (tid < H_DIM) { ybs[tid] = g_yb[tid]; w2ms[tid] = g_w2m[tid]; }
    __syncthreads();

    int n = blockIdx.x * 256 + tid;
    float h[H_DIM];
#pragma unroll
    for (int p = 0; p < H_DIM; p++) h[p] = g_H1[p * N_TOT + n];

    float xm = g_b2m;
#pragma unroll
    for (int p = 0; p < H_DIM; p++) xm = fmaf(w2ms[p], h[p], xm);
    g_xm[n] = xm;

    for (int o = 0; o < H_DIM; o++) {
        float a = ybs[o];
#pragma unroll
        for (int p = 0; p < H_DIM; p++) a = fmaf(Ms[o * H_DIM + p], h[p], a);
        g_Y[o * N_TOT + n] = a;
    }
}

// ---------------- K4: H2 = relu((Y @ expScore)*invZ + b3)  [verbatim] ------
__global__ void __launch_bounds__(256) k4_H2(const float* __restrict__ b3)
{
    __shared__ float yt[72 * 32];                       // [o][cl]
    __shared__ __align__(16) float at[32 * 128];        // [cl][dl]
    __shared__ float xsh[512];
    __shared__ __align__(16) float invZs[128];
    int g = blockIdx.y;
    int d0 = blockIdx.x * 128;
    int nb = g * 512;
    int tid = threadIdx.x;
    int dq = tid & 31, og = tid >> 5;

    for (int e = tid; e < 512; e += 256) xsh[e] = g_xm[nb + e];
    __syncthreads();

    if (tid < 128) {
        float xd = xsh[d0 + tid];
        float sum = 0.f;
        for (int c = 0; c < 512; c++) {
            float df = xsh[c] - xd;
            sum += __expf(-df * df);
        }
        invZs[tid] = 1.f / sum;
    }

    float acc[9][4];
#pragma unroll
    for (int k = 0; k < 9; k++)
#pragma unroll
        for (int j = 0; j < 4; j++) acc[k][j] = 0.f;

    for (int t = 0; t < 16; t++) {
        int c0 = t * 32;
        for (int e = tid; e < 72 * 32; e += 256) {
            int o = e >> 5, cl = e & 31;
            yt[e] = g_Y[o * N_TOT + nb + c0 + cl];
        }
        for (int e = tid; e < 32 * 128; e += 256) {
            int cl = e >> 7, dl = e & 127;
            float df = xsh[c0 + cl] - xsh[d0 + dl];
            at[e] = __expf(-df * df);
        }
        __syncthreads();
        for (int cl = 0; cl < 32; cl++) {
            float4 av = *(const float4*)&at[cl * 128 + dq * 4];
#pragma unroll
            for (int k = 0; k < 9; k++) {
                float yv = yt[(og * 9 + k) * 32 + cl];
                acc[k][0] = fmaf(yv, av.x, acc[k][0]);
                acc[k][1] = fmaf(yv, av.y, acc[k][1]);
                acc[k][2] = fmaf(yv, av.z, acc[k][2]);
                acc[k][3] = fmaf(yv, av.w, acc[k][3]);
            }
        }
        __syncthreads();
    }
    float4 inv = *(const float4*)&invZs[dq * 4];
#pragma unroll
    for (int k = 0; k < 9; k++) {
        int o = og * 9 + k;
        float bb = b3[o];
        float4 v;
        v.x = fmaxf(fmaf(acc[k][0], inv.x, bb), 0.f);
        v.y = fmaxf(fmaf(acc[k][1], inv.y, bb), 0.f);
        v.z = fmaxf(fmaf(acc[k][2], inv.z, bb), 0.f);
        v.w = fmaxf(fmaf(acc[k][3], inv.w, bb), 0.f);
        *(float4*)&g_H2[o * N_TOT + nb + d0 + dq * 4] = v;
    }
}

// ---------------- K5: out2 = W4 @ H2 + b4  + fused BN partials  [verbatim] -
__global__ void __launch_bounds__(256) k5_out2(const float* __restrict__ W4,
                                               const float* __restrict__ b4)
{
    extern __shared__ float ht[];                  // [72][128] = 36864 B
    __shared__ float ws[64 * 73];                  // [j][p + pad]
    __shared__ float b4s[64];
    int n0 = blockIdx.x * 128;
    int s0 = blockIdx.y * 64;
    int tid = threadIdx.x;
    int nl = tid & 31, sg = tid >> 5;

    for (int e = tid; e < H_DIM * 128; e += 256) {
        int p = e >> 7, cl = e & 127;
        ht[e] = g_H2[p * N_TOT + n0 + cl];
    }
    for (int e = tid; e < 64 * H_DIM; e += 256) {
        int j = e / H_DIM, p = e - j * H_DIM;
        ws[j * 73 + p] = W4[(s0 + j) * H_DIM + p];
    }
    if (tid < 64) b4s[tid] = b4[s0 + tid];
    __syncthreads();

    float acc[8][4];
#pragma unroll
    for (int k = 0; k < 8; k++)
#pragma unroll
        for (int j = 0; j < 4; j++) acc[k][j] = 0.f;

#pragma unroll 4
    for (int p = 0; p < H_DIM; p++) {
        float4 av = *(const float4*)&ht[p * 128 + nl * 4];
#pragma unroll
        for (int k = 0; k < 8; k++) {
            float w = ws[(sg * 8 + k) * 73 + p];
            acc[k][0] = fmaf(w, av.x, acc[k][0]);
            acc[k][1] = fmaf(w, av.y, acc[k][1]);
            acc[k][2] = fmaf(w, av.z, acc[k][2]);
            acc[k][3] = fmaf(w, av.w, acc[k][3]);
        }
    }
#pragma unroll
    for (int k = 0; k < 8; k++) {
        int s = s0 + sg * 8 + k;
        float bb = b4s[sg * 8 + k];
        float4 v;
        v.x = acc[k][0] + bb; v.y = acc[k][1] + bb;
        v.z = acc[k][2] + bb; v.w = acc[k][3] + bb;
        *(float4*)&g_out2[s * N_TOT + n0 + nl * 4] = v;

        float sm = (v.x + v.y) + (v.z + v.w);
        float sq = (v.x * v.x + v.y * v.y) + (v.z * v.z + v.w * v.w);
#pragma unroll
        for (int off = 16; off; off >>= 1) {
            sm += __shfl_down_sync(0xffffffffu, sm, off);
            sq += __shfl_down_sync(0xffffffffu, sq, off);
        }
        if (nl == 0) {
            g_psum[s * 512 + blockIdx.x] = sm;
            g_psq [s * 512 + blockIdx.x] = sq;
        }
    }
}

// ---------------- K6r: deterministic reduction of BN partials  [verbatim] --
__global__ void __launch_bounds__(256) k6_reduce(void)
{
    __shared__ float s1[8], s2[8];
    int s = blockIdx.x;
    int tid = threadIdx.x;
    float a = 0.f, q = 0.f;
    for (int i = tid; i < 512; i += 256) {
        a += g_psum[s * 512 + i];
        q += g_psq [s * 512 + i];
    }
#pragma unroll
    for (int off = 16; off; off >>= 1) {
        a += __shfl_down_sync(0xffffffffu, a, off);
        q += __shfl_down_sync(0xffffffffu, q, off);
    }
    int w = tid >> 5, l = tid & 31;
    if (l == 0) { s1[w] = a; s2[w] = q; }
    __syncthreads();
    if (tid == 0) {
        float aa = 0.f, qq = 0.f;
        for (int i = 0; i < 8; i++) { aa += s1[i]; qq += s2[i]; }
        float mu = aa * (1.f / (float)N_TOT);
        float var = qq * (1.f / (float)N_TOT) - mu * mu;
        g_mu[s] = mu;
        g_rstd[s] = rsqrtf(var + 1e-5f);
    }
}

// ---------------- K7: normalize + scatter + residual + relu  [verbatim] ----
__global__ void __launch_bounds__(256) k7_final(
    const float* __restrict__ x, const float* __restrict__ gamma,
    const float* __restrict__ beta, float* __restrict__ out)
{
    extern __shared__ float tile[];         // [s][33]
    int B  = blockIdx.y;
    int c0 = blockIdx.x * 32;
    int n0 = B * 1024 + c0;
    int tid = threadIdx.x;

    for (int e = tid; e < S_DIM * 32; e += 256) {
        int s = e >> 5, cl = e & 31;
        float rs = g_rstd[s], ga = gamma[s];
        float a  = rs * ga * 0.25f;
        float bb = (beta[s] - g_mu[s] * rs * ga) * 0.25f;
        tile[s * 33 + cl] = fmaf(g_out2[s * N_TOT + n0 + cl], a, bb);
    }
    __syncthreads();

    int b = B & 15, chunk = B >> 4;
    int ty = (chunk >> 1) * 24, tx = (chunk & 1) * 24;
    const float* xb = x   + (b * 1024 + c0) * 2304 + ty * 48 + tx;
    float*       ob = out + (b * 1024 + c0) * 2304 + ty * 48 + tx;

    for (int e = tid; e < 32 * S_DIM; e += 256) {
        int c = e / 576, s = e - c * 576;
        int si = s / 24, sj = s - si * 24;
        int addr = c * 2304 + si * 48 + sj;
        ob[addr] = fmaxf(xb[addr] + tile[s * 33 + c], 0.f);
    }
}

// ---------------- host launch ---------------------------------------------
extern "C" void kernel_launch(void* const* d_in, const int* in_sizes, int n_in,
                              void* d_out, int out_size)
{
    const float* x     = (const float*)d_in[0];
    const float* w1    = (const float*)d_in[1];
    const float* b1    = (const float*)d_in[2];
    const float* w2    = (const float*)d_in[3];
    const float* b2    = (const float*)d_in[4];
    const float* w3    = (const float*)d_in[5];
    const float* b3    = (const float*)d_in[6];
    const float* w4    = (const float*)d_in[7];
    const float* b4    = (const float*)d_in[8];
    const float* gamma = (const float*)d_in[9];
    const float* beta  = (const float*)d_in[10];
    float* out = (float*)d_out;

    cudaFuncSetAttribute(k5_out2, cudaFuncAttributeMaxDynamicSharedMemorySize,
                         H_DIM * 128 * 4);
    cudaFuncSetAttribute(k7_final, cudaFuncAttributeMaxDynamicSharedMemorySize,
                         S_DIM * 33 * 4);

    // 3 tiny prep launches FIRST so k1 is my 4th launch -> ncu (-s 5 -c 1)
    // captures the gemm1 kernel this round.
    k0a_M<<<72, 128>>>(w2, w3);
    k0b_yb<<<1, 128>>>(b2, w3);
    k0c_means<<<1, 128>>>(w2, b2);
    k1_gather_gemm1<<<512, 256, 48 * 132 * 4>>>(x, w1, b1);
    k2_Y_xm<<<256, 256>>>();
    k4_H2<<<dim3(4, 128), 256>>>(b3);
    k5_out2<<<dim3(512, 9), 256, H_DIM * 128 * 4>>>(w4, b4);
    k6_reduce<<<S_DIM, 256>>>();
    k7_final<<<dim3(32, 64), 256, S_DIM * 33 * 4>>>(x, gamma, beta, out);
}

// round 9
// speedup vs baseline: 1.2825x; 1.2825x over previous
#include <cuda_runtime.h>
#include <math.h>

#define N_TOT 65536      // B(64) * C(1024) columns
#define S_DIM 576
#define H_DIM 72

// ---------------- scratch (device globals; no allocation allowed) ----------
__device__ float g_H1[H_DIM * N_TOT];          // 18.9 MB
__device__ float g_Y [H_DIM * N_TOT];          // 18.9 MB
__device__ float g_H2[H_DIM * N_TOT];          // 18.9 MB
__device__ float g_xm[N_TOT];
__device__ float g_out2[S_DIM * N_TOT];        // 151 MB
__device__ float g_psum[S_DIM * 512];          // BN partials per (s, ntile)
__device__ float g_psq [S_DIM * 512];
__device__ float g_M[H_DIM * H_DIM];
__device__ float g_yb[H_DIM];
__device__ float g_w2m[H_DIM];
__device__ float g_b2m;
__device__ float g_mu[S_DIM];
__device__ float g_rstd[S_DIM];

// ---------------- K0: merged prep (74 blocks) ------------------------------
// blocks 0..71: M rows; block 72: yb; block 73: w2m/b2m
__global__ void __launch_bounds__(128) k0_prep(const float* __restrict__ W2,
                                               const float* __restrict__ b2,
                                               const float* __restrict__ W3)
{
    __shared__ float row[S_DIM];
    int o = blockIdx.x;
    if (o < H_DIM) {
        for (int e = threadIdx.x; e < S_DIM; e += 128) row[e] = W3[o * S_DIM + e];
        __syncthreads();
        if (threadIdx.x < H_DIM) {
            int j = threadIdx.x;
            float a = 0.f;
            for (int s = 0; s < S_DIM; s++) a = fmaf(row[s], W2[s * H_DIM + j], a);
            g_M[o * H_DIM + j] = a;
        }
    } else if (o == H_DIM) {
        for (int e = threadIdx.x; e < S_DIM; e += 128) row[e] = b2[e];
        __syncthreads();
        if (threadIdx.x < H_DIM) {
            int oo = threadIdx.x;
            float a = 0.f;
            for (int s = 0; s < S_DIM; s++) a = fmaf(W3[oo * S_DIM + s], row[s], a);
            g_yb[oo] = a;
        }
    } else {
        if (threadIdx.x < H_DIM) {
            int j = threadIdx.x;
            float a = 0.f;
            for (int s = 0; s < S_DIM; s++) a += W2[s * H_DIM + j];
            g_w2m[j] = a * (1.f / (float)S_DIM);
        }
        if (threadIdx.x == H_DIM) {
            float a = 0.f;
            for (int s = 0; s < S_DIM; s++) a += b2[s];
            g_b2m = a * (1.f / (float)S_DIM);
        }
    }
}

// ---------------- K1: fused gather + H1 = relu(W1 @ x_v + b1) --------------
// round-7 version: 128-col blocks, 9x4 register tile, 96-row s-tiles
// (6 fat phases, 2 blocks/SM — measured-best configuration ~150 us)
__global__ void __launch_bounds__(256) k1_gather_gemm1(
    const float* __restrict__ x,  const float* __restrict__ W1,
    const float* __restrict__ b1)
{
    __shared__ __align__(16) float wt[96 * 100];   // [sl][og*12 + k], 38.4 KB
    extern __shared__ __align__(16) float xt[];    // [96][132] = 50.7 KB dyn

    int n0 = blockIdx.x * 128;
    int B  = n0 >> 10;
    int c0 = n0 & 1023;
    int b = B & 15, chunk = B >> 4;
    int ty = (chunk >> 1) * 24, tx = (chunk & 1) * 24;
    int tid = threadIdx.x;
    int nl = tid & 31, og = tid >> 5;

    const float* xb = x + (b * 1024 + c0) * 2304 + ty * 48 + tx;

    float acc[9][4];
#pragma unroll
    for (int k = 0; k < 9; k++)
#pragma unroll
        for (int j = 0; j < 4; j++) acc[k][j] = 0.f;

    for (int t = 0; t < 6; t++) {
        for (int e = tid; e < 96 * 128; e += 256) {
            int cl = e / 96, sl = e - cl * 96;
            int s = t * 96 + sl;
            int si = s / 24, sj = s - si * 24;
            xt[sl * 132 + cl] = xb[cl * 2304 + si * 48 + sj];
        }
        for (int e = tid; e < 72 * 96; e += 256) {
            int o = e / 96, sl = e - o * 96;
            int oq = o / 9, ok = o - oq * 9;
            wt[sl * 100 + oq * 12 + ok] = W1[o * S_DIM + t * 96 + sl];
        }
        __syncthreads();
#pragma unroll 4
        for (int sl = 0; sl < 96; sl++) {
            float4 av = *(const float4*)&xt[sl * 132 + nl * 4];
            const float* wp = &wt[sl * 100 + og * 12];
            float4 w0 = *(const float4*)wp;
            float4 w1 = *(const float4*)(wp + 4);
            float  w8 = wp[8];
            acc[0][0] = fmaf(w0.x, av.x, acc[0][0]); acc[0][1] = fmaf(w0.x, av.y, acc[0][1]);
            acc[0][2] = fmaf(w0.x, av.z, acc[0][2]); acc[0][3] = fmaf(w0.x, av.w, acc[0][3]);
            acc[1][0] = fmaf(w0.y, av.x, acc[1][0]); acc[1][1] = fmaf(w0.y, av.y, acc[1][1]);
            acc[1][2] = fmaf(w0.y, av.z, acc[1][2]); acc[1][3] = fmaf(w0.y, av.w, acc[1][3]);
            acc[2][0] = fmaf(w0.z, av.x, acc[2][0]); acc[2][1] = fmaf(w0.z, av.y, acc[2][1]);
            acc[2][2] = fmaf(w0.z, av.z, acc[2][2]); acc[2][3] = fmaf(w0.z, av.w, acc[2][3]);
            acc[3][0] = fmaf(w0.w, av.x, acc[3][0]); acc[3][1] = fmaf(w0.w, av.y, acc[3][1]);
            acc[3][2] = fmaf(w0.w, av.z, acc[3][2]); acc[3][3] = fmaf(w0.w, av.w, acc[3][3]);
            acc[4][0] = fmaf(w1.x, av.x, acc[4][0]); acc[4][1] = fmaf(w1.x, av.y, acc[4][1]);
            acc[4][2] = fmaf(w1.x, av.z, acc[4][2]); acc[4][3] = fmaf(w1.x, av.w, acc[4][3]);
            acc[5][0] = fmaf(w1.y, av.x, acc[5][0]); acc[5][1] = fmaf(w1.y, av.y, acc[5][1]);
            acc[5][2] = fmaf(w1.y, av.z, acc[5][2]); acc[5][3] = fmaf(w1.y, av.w, acc[5][3]);
            acc[6][0] = fmaf(w1.z, av.x, acc[6][0]); acc[6][1] = fmaf(w1.z, av.y, acc[6][1]);
            acc[6][2] = fmaf(w1.z, av.z, acc[6][2]); acc[6][3] = fmaf(w1.z, av.w, acc[6][3]);
            acc[7][0] = fmaf(w1.w, av.x, acc[7][0]); acc[7][1] = fmaf(w1.w, av.y, acc[7][1]);
            acc[7][2] = fmaf(w1.w, av.z, acc[7][2]); acc[7][3] = fmaf(w1.w, av.w, acc[7][3]);
            acc[8][0] = fmaf(w8,   av.x, acc[8][0]); acc[8][1] = fmaf(w8,   av.y, acc[8][1]);
            acc[8][2] = fmaf(w8,   av.z, acc[8][2]); acc[8][3] = fmaf(w8,   av.w, acc[8][3]);
        }
        __syncthreads();
    }
#pragma unroll
    for (int k = 0; k < 9; k++) {
        int o = og * 9 + k;
        float bb = b1[o];
        float4 v;
        v.x = fmaxf(acc[k][0] + bb, 0.f);
        v.y = fmaxf(acc[k][1] + bb, 0.f);
        v.z = fmaxf(acc[k][2] + bb, 0.f);
        v.w = fmaxf(acc[k][3] + bb, 0.f);
        *(float4*)&g_H1[o * N_TOT + n0 + nl * 4] = v;
    }
}

// ---------------- K2: Y = M@H1 + yb ;  x_m = w2m@H1 + b2m  [verbatim] ------
__global__ void __launch_bounds__(256) k2_Y_xm(void)
{
    __shared__ float Ms[H_DIM * H_DIM];
    __shared__ float ybs[H_DIM], w2ms[H_DIM];
    int tid = threadIdx.x;
    for (int e = tid; e < H_DIM * H_DIM; e += 256) Ms[e] = g_M[e];
    if (tid < H_DIM) { ybs[tid] = g_yb[tid]; w2ms[tid] = g_w2m[tid]; }
    __syncthreads();

    int n = blockIdx.x * 256 + tid;
    float h[H_DIM];
#pragma unroll
    for (int p = 0; p < H_DIM; p++) h[p] = g_H1[p * N_TOT + n];

    float xm = g_b2m;
#pragma unroll
    for (int p = 0; p < H_DIM; p++) xm = fmaf(w2ms[p], h[p], xm);
    g_xm[n] = xm;

    for (int o = 0; o < H_DIM; o++) {
        float a = ybs[o];
#pragma unroll
        for (int p = 0; p < H_DIM; p++) a = fmaf(Ms[o * H_DIM + p], h[p], a);
        g_Y[o * N_TOT + n] = a;
    }
}

// ---------------- K4: H2 = relu((Y @ expScore)*invZ + b3)  [verbatim] ------
// 4th launch this round -> gets the ncu capture
__global__ void __launch_bounds__(256) k4_H2(const float* __restrict__ b3)
{
    __shared__ float yt[72 * 32];                       // [o][cl]
    __shared__ __align__(16) float at[32 * 128];        // [cl][dl]
    __shared__ float xsh[512];
    __shared__ __align__(16) float invZs[128];
    int g = blockIdx.y;
    int d0 = blockIdx.x * 128;
    int nb = g * 512;
    int tid = threadIdx.x;
    int dq = tid & 31, og = tid >> 5;

    for (int e = tid; e < 512; e += 256) xsh[e] = g_xm[nb + e];
    __syncthreads();

    if (tid < 128) {
        float xd = xsh[d0 + tid];
        float sum = 0.f;
        for (int c = 0; c < 512; c++) {
            float df = xsh[c] - xd;
            sum += __expf(-df * df);
        }
        invZs[tid] = 1.f / sum;
    }

    float acc[9][4];
#pragma unroll
    for (int k = 0; k < 9; k++)
#pragma unroll
        for (int j = 0; j < 4; j++) acc[k][j] = 0.f;

    for (int t = 0; t < 16; t++) {
        int c0 = t * 32;
        for (int e = tid; e < 72 * 32; e += 256) {
            int o = e >> 5, cl = e & 31;
            yt[e] = g_Y[o * N_TOT + nb + c0 + cl];
        }
        for (int e = tid; e < 32 * 128; e += 256) {
            int cl = e >> 7, dl = e & 127;
            float df = xsh[c0 + cl] - xsh[d0 + dl];
            at[e] = __expf(-df * df);
        }
        __syncthreads();
        for (int cl = 0; cl < 32; cl++) {
            float4 av = *(const float4*)&at[cl * 128 + dq * 4];
#pragma unroll
            for (int k = 0; k < 9; k++) {
                float yv = yt[(og * 9 + k) * 32 + cl];
                acc[k][0] = fmaf(yv, av.x, acc[k][0]);
                acc[k][1] = fmaf(yv, av.y, acc[k][1]);
                acc[k][2] = fmaf(yv, av.z, acc[k][2]);
                acc[k][3] = fmaf(yv, av.w, acc[k][3]);
            }
        }
        __syncthreads();
    }
    float4 inv = *(const float4*)&invZs[dq * 4];
#pragma unroll
    for (int k = 0; k < 9; k++) {
        int o = og * 9 + k;
        float bb = b3[o];
        float4 v;
        v.x = fmaxf(fmaf(acc[k][0], inv.x, bb), 0.f);
        v.y = fmaxf(fmaf(acc[k][1], inv.y, bb), 0.f);
        v.z = fmaxf(fmaf(acc[k][2], inv.z, bb), 0.f);
        v.w = fmaxf(fmaf(acc[k][3], inv.w, bb), 0.f);
        *(float4*)&g_H2[o * N_TOT + nb + d0 + dq * 4] = v;
    }
}

// ---------------- K5: out2 = W4 @ H2 + b4  + fused BN partials  [verbatim] -
__global__ void __launch_bounds__(256) k5_out2(const float* __restrict__ W4,
                                               const float* __restrict__ b4)
{
    extern __shared__ float ht[];                  // [72][128] = 36864 B
    __shared__ float ws[64 * 73];                  // [j][p + pad]
    __shared__ float b4s[64];
    int n0 = blockIdx.x * 128;
    int s0 = blockIdx.y * 64;
    int tid = threadIdx.x;
    int nl = tid & 31, sg = tid >> 5;

    for (int e = tid; e < H_DIM * 128; e += 256) {
        int p = e >> 7, cl = e & 127;
        ht[e] = g_H2[p * N_TOT + n0 + cl];
    }
    for (int e = tid; e < 64 * H_DIM; e += 256) {
        int j = e / H_DIM, p = e - j * H_DIM;
        ws[j * 73 + p] = W4[(s0 + j) * H_DIM + p];
    }
    if (tid < 64) b4s[tid] = b4[s0 + tid];
    __syncthreads();

    float acc[8][4];
#pragma unroll
    for (int k = 0; k < 8; k++)
#pragma unroll
        for (int j = 0; j < 4; j++) acc[k][j] = 0.f;

#pragma unroll 4
    for (int p = 0; p < H_DIM; p++) {
        float4 av = *(const float4*)&ht[p * 128 + nl * 4];
#pragma unroll
        for (int k = 0; k < 8; k++) {
            float w = ws[(sg * 8 + k) * 73 + p];
            acc[k][0] = fmaf(w, av.x, acc[k][0]);
            acc[k][1] = fmaf(w, av.y, acc[k][1]);
            acc[k][2] = fmaf(w, av.z, acc[k][2]);
            acc[k][3] = fmaf(w, av.w, acc[k][3]);
        }
    }
#pragma unroll
    for (int k = 0; k < 8; k++) {
        int s = s0 + sg * 8 + k;
        float bb = b4s[sg * 8 + k];
        float4 v;
        v.x = acc[k][0] + bb; v.y = acc[k][1] + bb;
        v.z = acc[k][2] + bb; v.w = acc[k][3] + bb;
        *(float4*)&g_out2[s * N_TOT + n0 + nl * 4] = v;

        float sm = (v.x + v.y) + (v.z + v.w);
        float sq = (v.x * v.x + v.y * v.y) + (v.z * v.z + v.w * v.w);
#pragma unroll
        for (int off = 16; off; off >>= 1) {
            sm += __shfl_down_sync(0xffffffffu, sm, off);
            sq += __shfl_down_sync(0xffffffffu, sq, off);
        }
        if (nl == 0) {
            g_psum[s * 512 + blockIdx.x] = sm;
            g_psq [s * 512 + blockIdx.x] = sq;
        }
    }
}

// ---------------- K6r: deterministic reduction of BN partials  [verbatim] --
__global__ void __launch_bounds__(256) k6_reduce(void)
{
    __shared__ float s1[8], s2[8];
    int s = blockIdx.x;
    int tid = threadIdx.x;
    float a = 0.f, q = 0.f;
    for (int i = tid; i < 512; i += 256) {
        a += g_psum[s * 512 + i];
        q += g_psq [s * 512 + i];
    }
#pragma unroll
    for (int off = 16; off; off >>= 1) {
        a += __shfl_down_sync(0xffffffffu, a, off);
        q += __shfl_down_sync(0xffffffffu, q, off);
    }
    int w = tid >> 5, l = tid & 31;
    if (l == 0) { s1[w] = a; s2[w] = q; }
    __syncthreads();
    if (tid == 0) {
        float aa = 0.f, qq = 0.f;
        for (int i = 0; i < 8; i++) { aa += s1[i]; qq += s2[i]; }
        float mu = aa * (1.f / (float)N_TOT);
        float var = qq * (1.f / (float)N_TOT) - mu * mu;
        g_mu[s] = mu;
        g_rstd[s] = rsqrtf(var + 1e-5f);
    }
}

// ---------------- K7: CHUNKED normalize + scatter + residual + relu --------
// grid (9 schunks, 32 ctiles, 64 B), block 256, smem 8.4 KB -> 8 blocks/SM
__global__ void __launch_bounds__(256) k7_final(
    const float* __restrict__ x, const float* __restrict__ gamma,
    const float* __restrict__ beta, float* __restrict__ out)
{
    __shared__ float tile[64 * 33];         // [sl][33]
    int s0 = blockIdx.x * 64;
    int c0 = blockIdx.y * 32;
    int B  = blockIdx.z;
    int n0 = B * 1024 + c0;
    int tid = threadIdx.x;

    // phase 1: normalize 64 s x 32 c chunk into smem (coalesced g_out2 reads)
#pragma unroll
    for (int e = tid; e < 64 * 32; e += 256) {
        int sl = e >> 5, cl = e & 31;
        int s = s0 + sl;
        float rs = g_rstd[s], ga = gamma[s];
        float a  = rs * ga * 0.25f;
        float bb = (beta[s] - g_mu[s] * rs * ga) * 0.25f;
        tile[sl * 33 + cl] = fmaf(g_out2[s * N_TOT + n0 + cl], a, bb);
    }
    __syncthreads();

    // phase 2: scatter (transposed): consecutive lanes -> consecutive sj
    int b = B & 15, chunk = B >> 4;
    int ty = (chunk >> 1) * 24, tx = (chunk & 1) * 24;
    const float* xb = x   + (b * 1024 + c0) * 2304 + ty * 48 + tx;
    float*       ob = out + (b * 1024 + c0) * 2304 + ty * 48 + tx;

#pragma unroll
    for (int e = tid; e < 32 * 64; e += 256) {
        int c = e >> 6, sl = e & 63;
        int s = s0 + sl;
        int si = s / 24, sj = s - si * 24;
        int addr = c * 2304 + si * 48 + sj;
        ob[addr] = fmaxf(xb[addr] + tile[sl * 33 + c], 0.f);
    }
}

// ---------------- host launch ---------------------------------------------
extern "C" void kernel_launch(void* const* d_in, const int* in_sizes, int n_in,
                              void* d_out, int out_size)
{
    const float* x     = (const float*)d_in[0];
    const float* w1    = (const float*)d_in[1];
    const float* b1    = (const float*)d_in[2];
    const float* w2    = (const float*)d_in[3];
    const float* b2    = (const float*)d_in[4];
    const float* w3    = (const float*)d_in[5];
    const float* b3    = (const float*)d_in[6];
    const float* w4    = (const float*)d_in[7];
    const float* b4    = (const float*)d_in[8];
    const float* gamma = (const float*)d_in[9];
    const float* beta  = (const float*)d_in[10];
    float* out = (float*)d_out;

    cudaFuncSetAttribute(k1_gather_gemm1, cudaFuncAttributeMaxDynamicSharedMemorySize,
                         96 * 132 * 4);
    cudaFuncSetAttribute(k5_out2, cudaFuncAttributeMaxDynamicSharedMemorySize,
                         H_DIM * 128 * 4);

    // launch order: k0, k1, k2, then k4 as my 4th launch -> ncu (-s 5 -c 1)
    // captures k4_H2 this round.
    k0_prep<<<74, 128>>>(w2, b2, w3);
    k1_gather_gemm1<<<512, 256, 96 * 132 * 4>>>(x, w1, b1);
    k2_Y_xm<<<256, 256>>>();
    k4_H2<<<dim3(4, 128), 256>>>(b3);
    k5_out2<<<dim3(512, 9), 256, H_DIM * 128 * 4>>>(w4, b4);
    k6_reduce<<<S_DIM, 256>>>();
    k7_final<<<dim3(9, 32, 64), 256>>>(x, gamma, beta, out);
}